// round 11
// baseline (speedup 1.0000x reference)
#include <cuda_runtime.h>
#include <cuda_fp16.h>
#include <cstdint>

// Problem constants
#define BSZ    256
#define HID    1024
#define TSTEPS 64
#define N4     4096
#define OUTW   64
#define INLEN  512

// GEMM tiling: per CTA M=128, N=64, K in BK=64 chunks (fp16), 512 threads (4m x 4n warps)
#define BM 128
#define BN 64
#define NKT 16                         // 1024 / 64
#define B_PERS_BYTES 131072            // 64 x 1024 fp16 persistent
#define A_SLOT_BYTES 16384             // 128 x 64 fp16
#define SMEM_BYTES (B_PERS_BYTES + 4 * A_SLOT_BYTES)   // 196608
#define NBLK 128
#define NTHR 512
#define A_MT_ELEMS 131072              // 128 rows * 1024 k (fp16) per m-tile
#define B_NT_ELEMS 65536               // 64 rows * 1024 k (fp16) per n-tile

// h0 split
#define H0S 8
#define H0ROWS (INLEN / H0S)

// ---------------- device scratch ----------------
__device__ __half g_Whp[N4 * HID];          // fragment-permuted w_hh          (step 0)
__device__ __half g_Wcp[N4 * HID];          // fragment-permuted w_ih + w_hh   (steps >=1)
__device__ __half g_WoutP[OUTW * HID];      // fragment-permuted w_out
__device__ float  g_g0[N4];
__device__ float  g_bp[N4];
__device__ __half g_act0[BSZ * HID];        // fragment-permuted activations (ping)
__device__ __half g_act1[BSZ * HID];        // (pong)
__device__ __half g_A2[BSZ * TSTEPS * HID]; // hiddens, fragment-permuted (projection A)
__device__ float  g_out[BSZ * TSTEPS * HID];// fallback hidden store
__device__ float4 g_part4[H0S * BSZ * (HID / 4)];
__device__ unsigned g_gbcount[2 * 32];      // per-mt group barrier (line-separated)
__device__ unsigned g_gbgen[2 * 32];
__device__ unsigned g_bar_count = 0;        // global barrier (projection only)
__device__ unsigned g_bar_gen   = 0;

// ---------------- helpers ----------------
__device__ __forceinline__ float sigm(float x) { return 1.0f / (1.0f + __expf(-x)); }
__device__ __forceinline__ float tanh_acc(float x) { return 2.0f / (1.0f + __expf(-2.0f * x)) - 1.0f; }

// A-side fragment-permuted index: [mt][kc16(64)][mb(8)][lane(32)][8 halves]
__device__ __forceinline__ size_t a_idx(int mt, int r, int k) {
    int kc = k >> 4, kk = k & 15;
    int mb = r >> 4, rl = r & 15;
    int lane = ((rl & 7) << 2) | ((kk >> 1) & 3);
    int idx8 = ((kk >> 3) << 2) | ((rl >> 3) << 1) | (kk & 1);
    return ((((size_t)mt * 64 + kc) * 8 + mb) * 32 + lane) * 8 + idx8;
}

__device__ __forceinline__ void cp16c(char* dst, const char* src) {
    uint32_t d = (uint32_t)__cvta_generic_to_shared(dst);
    asm volatile("cp.async.cg.shared.global [%0], [%1], 16;\n" :: "r"(d), "l"(src));
}
__device__ __forceinline__ void mma_f16(float* c, const float4& a, float bx, float by) {
    asm volatile(
        "mma.sync.aligned.m16n8k16.row.col.f32.f16.f16.f32 "
        "{%0,%1,%2,%3}, {%4,%5,%6,%7}, {%8,%9}, {%0,%1,%2,%3};\n"
        : "+f"(c[0]), "+f"(c[1]), "+f"(c[2]), "+f"(c[3])
        : "r"(__float_as_uint(a.x)), "r"(__float_as_uint(a.y)),
          "r"(__float_as_uint(a.z)), "r"(__float_as_uint(a.w)),
          "r"(__float_as_uint(bx)), "r"(__float_as_uint(by)));
}

__device__ __forceinline__ void barrier_impl(unsigned* cnt, unsigned* gen, unsigned n) {
    __syncthreads();
    if (threadIdx.x == 0) {
        unsigned g;
        asm volatile("ld.acquire.gpu.u32 %0, [%1];" : "=r"(g) : "l"(gen) : "memory");
        unsigned old;
        asm volatile("atom.release.gpu.add.u32 %0, [%1], %2;"
                     : "=r"(old) : "l"(cnt), "r"(1u) : "memory");
        if (old == n - 1) {
            asm volatile("st.relaxed.gpu.u32 [%0], %1;" :: "l"(cnt), "r"(0u) : "memory");
            asm volatile("st.release.gpu.u32 [%0], %1;" :: "l"(gen), "r"(g + 1u) : "memory");
        } else {
            unsigned cur;
            do {
                asm volatile("ld.acquire.gpu.u32 %0, [%1];" : "=r"(cur) : "l"(gen) : "memory");
            } while (cur == g);
        }
    }
    __syncthreads();
}

// ---------------- prep kernels ----------------
__global__ void prep_weights(const float* __restrict__ w_ih, const float* __restrict__ w_hh) {
    int gid  = blockIdx.x * 256 + threadIdx.x;   // 0 .. N4*HID-1
    int idx8 = gid & 7;
    int lane = (gid >> 3) & 31;
    int nb   = (gid >> 8) & 7;
    int kc32 = (gid >> 11) & 31;
    int nt   = gid >> 16;
    int c  = lane >> 2;
    int g4 = lane & 3;
    int kk = ((idx8 >> 1) & 1) * 8 + g4 * 2 + (idx8 & 1);
    int k  = kc32 * 32 + (idx8 >> 2) * 16 + kk;
    int np = nt * 64 + nb * 8 + c;
    int h = np >> 2, gate = np & 3;
    int j = (gate << 10) + h;
    float whh = w_hh[(size_t)j * HID + k];
    float wc  = w_ih[(size_t)j * HID + k] + whh;
    g_Whp[gid] = __float2half_rn(whh);
    g_Wcp[gid] = __float2half_rn(wc);
}

__global__ void prep_wout(const float* __restrict__ w_out) {
    int gid  = blockIdx.x * 256 + threadIdx.x;   // 0 .. 65535
    int idx8 = gid & 7;
    int lane = (gid >> 3) & 31;
    int nb   = (gid >> 8) & 7;
    int kc32 = (gid >> 11) & 31;
    int c  = lane >> 2;
    int g4 = lane & 3;
    int kk = ((idx8 >> 1) & 1) * 8 + g4 * 2 + (idx8 & 1);
    int k  = kc32 * 32 + (idx8 >> 2) * 16 + kk;
    int j  = nb * 8 + c;
    g_WoutP[gid] = __float2half_rn(w_out[(size_t)j * HID + k]);
}

__global__ void prep_bias(const float* __restrict__ st, const float* __restrict__ w_ih,
                          const float* __restrict__ b_ih, const float* __restrict__ b_hh) {
    int gw   = (blockIdx.x * blockDim.x + threadIdx.x) >> 5;
    int lane = threadIdx.x & 31;
    for (int np = gw; np < N4; np += 1024) {
        int h = np >> 2, g = np & 3;
        int j = (g << 10) + h;
        const float* wr = w_ih + (size_t)j * HID;
        float s = 0.f;
        #pragma unroll 8
        for (int k = lane; k < HID; k += 32) s += st[k] * wr[k];
        #pragma unroll
        for (int off = 16; off > 0; off >>= 1) s += __shfl_xor_sync(0xffffffffu, s, off);
        if (lane == 0) {
            float bs = b_ih[j] + b_hh[j];
            g_bp[np] = bs;
            g_g0[np] = s + bs;
        }
    }
}

// ---------------- h0 ----------------
__global__ void h0_part(const float* __restrict__ qf, const float* __restrict__ w_in) {
    __shared__ float sw[H0ROWS];
    int b = blockIdx.x, s = blockIdx.y, tid = threadIdx.x;
    if (tid < H0ROWS) sw[tid] = w_in[s * H0ROWS + tid];
    __syncthreads();
    const float4* q = reinterpret_cast<const float4*>(qf)
                    + ((size_t)b * INLEN + s * H0ROWS) * (HID / 4) + tid;
    float4 acc = make_float4(0.f, 0.f, 0.f, 0.f);
    #pragma unroll 16
    for (int i = 0; i < H0ROWS; i++) {
        float4 v = q[(size_t)i * (HID / 4)];
        float w = sw[i];
        acc.x = fmaf(v.x, w, acc.x);
        acc.y = fmaf(v.y, w, acc.y);
        acc.z = fmaf(v.z, w, acc.z);
        acc.w = fmaf(v.w, w, acc.w);
    }
    g_part4[((size_t)s * BSZ + b) * (HID / 4) + tid] = acc;
}

__global__ void h0_comb(const float* __restrict__ b_in) {
    int b = blockIdx.x, tid = threadIdx.x;
    float4 a = make_float4(0.f, 0.f, 0.f, 0.f);
    #pragma unroll
    for (int s = 0; s < H0S; s++) {
        float4 p = g_part4[((size_t)s * BSZ + b) * (HID / 4) + tid];
        a.x += p.x; a.y += p.y; a.z += p.z; a.w += p.w;
    }
    float bb = b_in[0];
    float v[4] = { a.x + bb, a.y + bb, a.z + bb, a.w + bb };
    int mt = b >> 7, row = b & 127;
    #pragma unroll
    for (int i = 0; i < 4; i++)
        g_act0[a_idx(mt, row, tid * 4 + i)] = __float2half_rn(v[i]);
}

// ---------------- GEMM core: persistent-B smem + 4-slot A pipeline, 512 threads ----------------
extern __shared__ char dynsm[];

__device__ __forceinline__ void stage_A(const __half* Ablk, int kt, int tid) {
    char* s = dynsm + B_PERS_BYTES + (size_t)(kt & 3) * A_SLOT_BYTES;
    const char* gA = (const char*)(Ablk + (size_t)kt * 8192);   // 128x64 fp16 = 16KB
    #pragma unroll
    for (int i = 0; i < 2; i++) { int o = (tid + i * NTHR) * 16; cp16c(s + o, gA + o); }
}
// full 128KB B tile -> persistent region
__device__ __forceinline__ void stage_Bfull(const __half* W, int tid) {
    const char* gB = (const char*)W;
    #pragma unroll
    for (int i = 0; i < 16; i++) { int o = (tid + i * NTHR) * 16; cp16c(dynsm + o, gB + o); }
}

// kt-loop; B-full group older than the 3 committed A groups
// warp grid 4m x 4n: warp tile 32 rows x 16 cols; acc[mb2][nb2][4]
__device__ __forceinline__ void gemm_loop(const __half* __restrict__ Ablk,
                                          float (&acc)[2][2][4],
                                          int tid, int lane, int wm, int wn) {
    #pragma unroll
    for (int i = 0; i < 2; i++)
        #pragma unroll
        for (int j = 0; j < 2; j++)
            #pragma unroll
            for (int r = 0; r < 4; r++) acc[i][j][r] = 0.f;

    #pragma unroll 1
    for (int kt = 0; kt < NKT; kt++) {
        if (kt < NKT - 2)       asm volatile("cp.async.wait_group 2;\n" ::: "memory");
        else if (kt == NKT - 2) asm volatile("cp.async.wait_group 1;\n" ::: "memory");
        else                    asm volatile("cp.async.wait_group 0;\n" ::: "memory");
        __syncthreads();
        if (kt + 3 < NKT) {
            stage_A(Ablk, kt + 3, tid);
            asm volatile("cp.async.commit_group;\n" ::: "memory");
        }
        const float4* A4 = reinterpret_cast<const float4*>(
            dynsm + B_PERS_BYTES + (size_t)(kt & 3) * A_SLOT_BYTES);
        const float4* B4 = reinterpret_cast<const float4*>(dynsm + (size_t)kt * 8192);

        float4 af[2][2];      // double-buffered A frags per kc16 (mb 0..1)
        float4 bq[2][2];      // B frags per kc32 half (nb 0..1)
        #pragma unroll
        for (int mb = 0; mb < 2; mb++) af[0][mb] = A4[(wm * 2 + mb) * 32 + lane];
        #pragma unroll
        for (int nb = 0; nb < 2; nb++) bq[0][nb] = B4[(wn * 2 + nb) * 32 + lane];

        #pragma unroll
        for (int kc = 0; kc < 4; kc++) {
            if (kc == 0) {
                #pragma unroll
                for (int nb = 0; nb < 2; nb++)
                    bq[1][nb] = B4[(8 + wn * 2 + nb) * 32 + lane];
            }
            if (kc < 3) {
                #pragma unroll
                for (int mb = 0; mb < 2; mb++)
                    af[(kc + 1) & 1][mb] = A4[((kc + 1) * 8 + wm * 2 + mb) * 32 + lane];
            }
            #pragma unroll
            for (int mb = 0; mb < 2; mb++)
                #pragma unroll
                for (int nb = 0; nb < 2; nb++) {
                    const float4& b4 = bq[kc >> 1][nb];
                    if (kc & 1) mma_f16(acc[mb][nb], af[kc & 1][mb], b4.z, b4.w);
                    else        mma_f16(acc[mb][nb], af[kc & 1][mb], b4.x, b4.y);
                }
        }
    }
    __syncthreads();   // all warps done reading A slots + B region before any reuse
}

// ---------------- persistent LSTM + projection ----------------
__global__ void __launch_bounds__(NTHR, 1)
lstm_persist(const float* __restrict__ b_out, float* __restrict__ probs_dst,
             float* __restrict__ hid_dst) {
    const int tid  = threadIdx.x;
    const int lane = tid & 31;
    const int w    = tid >> 5;       // 0..15
    const int wm   = w & 3;          // 4 m-warps (32 rows each)
    const int wn   = w >> 2;         // 4 n-warps (16 cols each)
    const int mt   = blockIdx.x;     // 0..1
    const int nt   = blockIdx.y;     // 0..63
    const int mBase = mt * BM;
    const int q    = (lane & 3) >> 1;          // h-group within 8-col span
    const int odd  = lane & 1;

    float* hout = (hid_dst != nullptr) ? hid_dst : g_out;

    float acc[2][2][4];
    float c_reg[4];                  // cell state: [mb*2+nb]
    #pragma unroll
    for (int i = 0; i < 4; i++) c_reg[i] = 0.f;

    // cached bias (steps >= 1): per nb the 4 gate biases of this thread's h-group
    float4 biasc[2];
    #pragma unroll
    for (int nb = 0; nb < 2; nb++) {
        int hl = wn * 4 + nb * 2 + q;
        biasc[nb] = *reinterpret_cast<const float4*>(&g_bp[nt * 64 + hl * 4]);
    }

    // load step-0 weights (w_hh) into persistent smem region
    stage_Bfull(g_Whp + (size_t)nt * B_NT_ELEMS, tid);
    asm volatile("cp.async.commit_group;\n" ::: "memory");

    #pragma unroll 1
    for (int t = 0; t < TSTEPS; t++) {
        const __half* A    = ((t & 1) ? g_act1 : g_act0) + (size_t)mt * A_MT_ELEMS;
        __half*       nact = (t & 1) ? g_act0 : g_act1;

        // prologue: stage A chunks 0..2 (B-full group is older)
        #pragma unroll
        for (int p = 0; p < 3; p++) {
            stage_A(A, p, tid);
            asm volatile("cp.async.commit_group;\n" ::: "memory");
        }
        gemm_loop(A, acc, tid, lane, wm, wn);

        // swap persistent B (overlaps epilogue + barrier)
        if (t == 0) {
            stage_Bfull(g_Wcp + (size_t)nt * B_NT_ELEMS, tid);
            asm volatile("cp.async.commit_group;\n" ::: "memory");
        } else if (t == TSTEPS - 1 && probs_dst != nullptr) {
            stage_Bfull(g_WoutP, tid);
            asm volatile("cp.async.commit_group;\n" ::: "memory");
        }

        // register epilogue: lane pairs exchange gate halves via shfl
        #pragma unroll
        for (int mb = 0; mb < 2; mb++)
            #pragma unroll
            for (int nb = 0; nb < 2; nb++) {
                float* a4 = acc[mb][nb];
                float s0 = odd ? a4[0] : a4[2];
                float s1 = odd ? a4[1] : a4[3];
                float r0 = __shfl_xor_sync(0xffffffffu, s0, 1);
                float r1 = __shfl_xor_sync(0xffffffffu, s1, 1);
                float gi, gf, gg, go;
                if (odd) { gi = r0;    gf = r1;    gg = a4[2]; go = a4[3]; }   // row r+8
                else     { gi = a4[0]; gf = a4[1]; gg = r0;    go = r1;   }   // row r
                int row = (wm * 2 + mb) * 16 + (lane >> 2) + (odd ? 8 : 0);
                int hl  = wn * 4 + nb * 2 + q;
                float4 bb = (t == 0)
                    ? *reinterpret_cast<const float4*>(&g_g0[nt * 64 + hl * 4])
                    : biasc[nb];
                gi += bb.x; gf += bb.y; gg += bb.z; go += bb.w;
                int ci = mb * 2 + nb;
                float cN = sigm(gf) * c_reg[ci] + sigm(gi) * tanh_acc(gg);
                float hN = sigm(go) * tanh_acc(cN);
                c_reg[ci] = cN;
                int b  = mBase + row;
                int hg = nt * 16 + hl;
                hout[((size_t)b * TSTEPS + t) * HID + hg] = hN;
                __half hv = __float2half_rn(hN);
                nact[a_idx(mt, row, hg)] = hv;
                int r2 = b * TSTEPS + t;
                g_A2[a_idx(r2 >> 7, r2 & 127, hg)] = hv;
            }

        // per-mt group barrier (64 CTAs): A(t+1) of this m-tile complete
        barrier_impl(&g_gbcount[mt * 32], &g_gbgen[mt * 32], 64u);
    }

    // projection: A2 [16384 x 1024] @ WoutP^T [64 x 1024] over 128 m-tiles
    if (probs_dst != nullptr) {
        barrier_impl(&g_bar_count, &g_bar_gen, (unsigned)NBLK);   // cross-group A2 ready
        int bid = mt + 2 * nt;               // 0..127
        const __half* A = g_A2 + (size_t)bid * A_MT_ELEMS;
        #pragma unroll
        for (int p = 0; p < 3; p++) {        // WoutP already loading into B region
            stage_A(A, p, tid);
            asm volatile("cp.async.commit_group;\n" ::: "memory");
        }
        gemm_loop(A, acc, tid, lane, wm, wn);
        int pBase = bid * BM;
        #pragma unroll
        for (int mb = 0; mb < 2; mb++)
            #pragma unroll
            for (int nb = 0; nb < 2; nb++) {
                int r0 = (wm * 2 + mb) * 16 + (lane >> 2);
                int c0 = (wn * 2 + nb) * 8 + (lane & 3) * 2;
                float2 b2 = *reinterpret_cast<const float2*>(&b_out[c0]);
                float2 v0 = make_float2(acc[mb][nb][0] + b2.x, acc[mb][nb][1] + b2.y);
                float2 v1 = make_float2(acc[mb][nb][2] + b2.x, acc[mb][nb][3] + b2.y);
                *reinterpret_cast<float2*>(&probs_dst[(size_t)(pBase + r0) * OUTW + c0]) = v0;
                *reinterpret_cast<float2*>(&probs_dst[(size_t)(pBase + r0 + 8) * OUTW + c0]) = v1;
            }
    }
}

// ---------------- host ----------------
extern "C" void kernel_launch(void* const* d_in, const int* in_sizes, int n_in,
                              void* d_out, int out_size) {
    const float* qf    = (const float*)d_in[1];
    const float* st    = (const float*)d_in[4];
    const float* w_in  = (const float*)d_in[5];
    const float* b_in  = (const float*)d_in[6];
    const float* w_ih  = (const float*)d_in[7];
    const float* w_hh  = (const float*)d_in[8];
    const float* b_ih  = (const float*)d_in[9];
    const float* b_hh  = (const float*)d_in[10];
    const float* w_out = (const float*)d_in[11];
    const float* b_out = (const float*)d_in[12];
    float* out = (float*)d_out;

    cudaFuncSetAttribute(lstm_persist, cudaFuncAttributeMaxDynamicSharedMemorySize, SMEM_BYTES);

    prep_weights<<<(N4 * HID) / 256, 256>>>(w_ih, w_hh);
    prep_wout<<<(OUTW * HID) / 256, 256>>>(w_out);
    prep_bias<<<128, 256>>>(st, w_ih, b_ih, b_hh);
    h0_part<<<dim3(BSZ, H0S), 256>>>(qf, w_in);
    h0_comb<<<BSZ, 256>>>(b_in);

    // output routing: reference returns (probs, output)
    const long long PROBS_N = (long long)BSZ * TSTEPS * OUTW;
    const long long OUT_N   = (long long)BSZ * TSTEPS * HID;
    float* probs_dst = nullptr;
    float* hid_dst   = nullptr;
    if ((long long)out_size >= PROBS_N + OUT_N) {
        probs_dst = out;
        hid_dst   = out + PROBS_N;
    } else if ((long long)out_size == OUT_N) {
        hid_dst = out;
    } else {
        probs_dst = out;
    }

    lstm_persist<<<dim3(2, 64), NTHR, SMEM_BYTES>>>(b_out, probs_dst, hid_dst);
}

// round 13
// speedup vs baseline: 1.1283x; 1.1283x over previous
#include <cuda_runtime.h>
#include <cuda_fp16.h>
#include <cstdint>

// Problem constants
#define BSZ    256
#define HID    1024
#define TSTEPS 64
#define N4     4096
#define OUTW   64
#define INLEN  512

// GEMM tiling: per CTA M=128, N=64, K in BK=128 chunks (fp16), 256 threads (4m x 2n warps)
#define BM 128
#define BN 64
#define NKT 8                          // 1024 / 128
#define B_PERS_BYTES 131072            // 64 x 1024 fp16 persistent
#define A_SLOT_BYTES 32768             // 128 x 128 fp16
#define NSLOT 3
#define SMEM_BYTES (B_PERS_BYTES + NSLOT * A_SLOT_BYTES)   // 229376
#define NBLK 128
#define NTHR 256
#define A_MT_ELEMS 131072              // 128 rows * 1024 k (fp16) per m-tile
#define B_NT_ELEMS 65536               // 64 rows * 1024 k (fp16) per n-tile

// h0 split
#define H0S 16
#define H0ROWS (INLEN / H0S)           // 32

// ---------------- device scratch ----------------
__device__ __half g_Whp[N4 * HID];          // fragment-permuted w_hh          (step 0)
__device__ __half g_Wcp[N4 * HID];          // fragment-permuted w_ih + w_hh   (steps >=1)
__device__ __half g_WoutP[OUTW * HID];      // fragment-permuted w_out
__device__ float  g_g0[N4];
__device__ float  g_bp[N4];
__device__ __half g_act0[BSZ * HID];        // fragment-permuted activations (ping)
__device__ __half g_act1[BSZ * HID];        // (pong)
__device__ __half g_A2[BSZ * TSTEPS * HID]; // hiddens, fragment-permuted (projection A)
__device__ float  g_out[BSZ * TSTEPS * HID];// fallback hidden store
__device__ float4 g_part4[H0S * BSZ * (HID / 4)];
__device__ unsigned g_gbcount[2 * 32];      // per-mt group barrier (line-separated)
__device__ unsigned g_gbgen[2 * 32];
__device__ unsigned g_bar_count = 0;        // global barrier (projection only)
__device__ unsigned g_bar_gen   = 0;

// ---------------- helpers ----------------
__device__ __forceinline__ float sigm(float x) { return 1.0f / (1.0f + __expf(-x)); }
__device__ __forceinline__ float tanh_acc(float x) { return 2.0f / (1.0f + __expf(-2.0f * x)) - 1.0f; }

// A-side fragment-permuted index: [mt][kc16(64)][mb(8)][lane(32)][8 halves]
__device__ __forceinline__ size_t a_idx(int mt, int r, int k) {
    int kc = k >> 4, kk = k & 15;
    int mb = r >> 4, rl = r & 15;
    int lane = ((rl & 7) << 2) | ((kk >> 1) & 3);
    int idx8 = ((kk >> 3) << 2) | ((rl >> 3) << 1) | (kk & 1);
    return ((((size_t)mt * 64 + kc) * 8 + mb) * 32 + lane) * 8 + idx8;
}

__device__ __forceinline__ void cp16c(char* dst, const char* src) {
    uint32_t d = (uint32_t)__cvta_generic_to_shared(dst);
    asm volatile("cp.async.cg.shared.global [%0], [%1], 16;\n" :: "r"(d), "l"(src));
}
__device__ __forceinline__ void mma_f16(float* c, const float4& a, float bx, float by) {
    asm volatile(
        "mma.sync.aligned.m16n8k16.row.col.f32.f16.f16.f32 "
        "{%0,%1,%2,%3}, {%4,%5,%6,%7}, {%8,%9}, {%0,%1,%2,%3};\n"
        : "+f"(c[0]), "+f"(c[1]), "+f"(c[2]), "+f"(c[3])
        : "r"(__float_as_uint(a.x)), "r"(__float_as_uint(a.y)),
          "r"(__float_as_uint(a.z)), "r"(__float_as_uint(a.w)),
          "r"(__float_as_uint(bx)), "r"(__float_as_uint(by)));
}

__device__ __forceinline__ void barrier_impl(unsigned* cnt, unsigned* gen, unsigned n) {
    __syncthreads();
    if (threadIdx.x == 0) {
        unsigned g;
        asm volatile("ld.acquire.gpu.u32 %0, [%1];" : "=r"(g) : "l"(gen) : "memory");
        unsigned old;
        asm volatile("atom.release.gpu.add.u32 %0, [%1], %2;"
                     : "=r"(old) : "l"(cnt), "r"(1u) : "memory");
        if (old == n - 1) {
            asm volatile("st.relaxed.gpu.u32 [%0], %1;" :: "l"(cnt), "r"(0u) : "memory");
            asm volatile("st.release.gpu.u32 [%0], %1;" :: "l"(gen), "r"(g + 1u) : "memory");
        } else {
            unsigned cur;
            do {
                asm volatile("ld.acquire.gpu.u32 %0, [%1];" : "=r"(cur) : "l"(gen) : "memory");
            } while (cur == g);
        }
    }
    __syncthreads();
}

// ---------------- prep kernels ----------------
__global__ void prep_weights(const float* __restrict__ w_ih, const float* __restrict__ w_hh) {
    int gid  = blockIdx.x * 256 + threadIdx.x;   // 0 .. N4*HID-1
    int idx8 = gid & 7;
    int lane = (gid >> 3) & 31;
    int nb   = (gid >> 8) & 7;
    int kc32 = (gid >> 11) & 31;
    int nt   = gid >> 16;
    int c  = lane >> 2;
    int g4 = lane & 3;
    int kk = ((idx8 >> 1) & 1) * 8 + g4 * 2 + (idx8 & 1);
    int k  = kc32 * 32 + (idx8 >> 2) * 16 + kk;
    int np = nt * 64 + nb * 8 + c;
    int h = np >> 2, gate = np & 3;
    int j = (gate << 10) + h;
    float whh = w_hh[(size_t)j * HID + k];
    float wc  = w_ih[(size_t)j * HID + k] + whh;
    g_Whp[gid] = __float2half_rn(whh);
    g_Wcp[gid] = __float2half_rn(wc);
}

__global__ void prep_wout(const float* __restrict__ w_out) {
    int gid  = blockIdx.x * 256 + threadIdx.x;   // 0 .. 65535
    int idx8 = gid & 7;
    int lane = (gid >> 3) & 31;
    int nb   = (gid >> 8) & 7;
    int kc32 = (gid >> 11) & 31;
    int c  = lane >> 2;
    int g4 = lane & 3;
    int kk = ((idx8 >> 1) & 1) * 8 + g4 * 2 + (idx8 & 1);
    int k  = kc32 * 32 + (idx8 >> 2) * 16 + kk;
    int j  = nb * 8 + c;
    g_WoutP[gid] = __float2half_rn(w_out[(size_t)j * HID + k]);
}

__global__ void prep_bias(const float* __restrict__ st, const float* __restrict__ w_ih,
                          const float* __restrict__ b_ih, const float* __restrict__ b_hh) {
    int gw   = (blockIdx.x * blockDim.x + threadIdx.x) >> 5;
    int lane = threadIdx.x & 31;
    for (int np = gw; np < N4; np += 1024) {
        int h = np >> 2, g = np & 3;
        int j = (g << 10) + h;
        const float* wr = w_ih + (size_t)j * HID;
        float s = 0.f;
        #pragma unroll 8
        for (int k = lane; k < HID; k += 32) s += st[k] * wr[k];
        #pragma unroll
        for (int off = 16; off > 0; off >>= 1) s += __shfl_xor_sync(0xffffffffu, s, off);
        if (lane == 0) {
            float bs = b_ih[j] + b_hh[j];
            g_bp[np] = bs;
            g_g0[np] = s + bs;
        }
    }
}

// ---------------- h0 ----------------
__global__ void h0_part(const float* __restrict__ qf, const float* __restrict__ w_in) {
    __shared__ float sw[H0ROWS];
    int b = blockIdx.x, s = blockIdx.y, tid = threadIdx.x;
    if (tid < H0ROWS) sw[tid] = w_in[s * H0ROWS + tid];
    __syncthreads();
    const float4* q = reinterpret_cast<const float4*>(qf)
                    + ((size_t)b * INLEN + s * H0ROWS) * (HID / 4) + tid;
    float4 acc = make_float4(0.f, 0.f, 0.f, 0.f);
    #pragma unroll 32
    for (int i = 0; i < H0ROWS; i++) {
        float4 v = q[(size_t)i * (HID / 4)];
        float w = sw[i];
        acc.x = fmaf(v.x, w, acc.x);
        acc.y = fmaf(v.y, w, acc.y);
        acc.z = fmaf(v.z, w, acc.z);
        acc.w = fmaf(v.w, w, acc.w);
    }
    g_part4[((size_t)s * BSZ + b) * (HID / 4) + tid] = acc;
}

__global__ void h0_comb(const float* __restrict__ b_in) {
    int b = blockIdx.x, tid = threadIdx.x;
    float4 a = make_float4(0.f, 0.f, 0.f, 0.f);
    #pragma unroll
    for (int s = 0; s < H0S; s++) {
        float4 p = g_part4[((size_t)s * BSZ + b) * (HID / 4) + tid];
        a.x += p.x; a.y += p.y; a.z += p.z; a.w += p.w;
    }
    float bb = b_in[0];
    float v[4] = { a.x + bb, a.y + bb, a.z + bb, a.w + bb };
    int mt = b >> 7, row = b & 127;
    #pragma unroll
    for (int i = 0; i < 4; i++)
        g_act0[a_idx(mt, row, tid * 4 + i)] = __float2half_rn(v[i]);
}

// ---------------- GEMM core: persistent-B smem + 3-slot 32KB A pipeline ----------------
extern __shared__ char dynsm[];

__device__ __forceinline__ char* a_slot(int kt) {
    return dynsm + B_PERS_BYTES + (size_t)(kt % NSLOT) * A_SLOT_BYTES;
}

__device__ __forceinline__ void stage_A(const __half* Ablk, int kt, int tid) {
    char* s = a_slot(kt);
    const char* gA = (const char*)(Ablk + (size_t)kt * 16384);   // 128x128 fp16 = 32KB
    #pragma unroll
    for (int i = 0; i < 8; i++) { int o = (tid + i * NTHR) * 16; cp16c(s + o, gA + o); }
}
// full 128KB B tile -> persistent region
__device__ __forceinline__ void stage_Bfull(const __half* W, int tid) {
    const char* gB = (const char*)W;
    #pragma unroll
    for (int i = 0; i < 32; i++) { int o = (tid + i * NTHR) * 16; cp16c(dynsm + o, gB + o); }
}

// kt-loop over 8 chunks of 128 k; B-full group older than the 2 committed A groups
__device__ __forceinline__ void gemm_loop(const __half* __restrict__ Ablk,
                                          float (&acc)[2][4][4],
                                          int tid, int lane, int wm, int wn) {
    #pragma unroll
    for (int i = 0; i < 2; i++)
        #pragma unroll
        for (int j = 0; j < 4; j++)
            #pragma unroll
            for (int r = 0; r < 4; r++) acc[i][j][r] = 0.f;

    #pragma unroll 1
    for (int kt = 0; kt < NKT; kt++) {
        if (kt < NKT - 1) asm volatile("cp.async.wait_group 1;\n" ::: "memory");
        else              asm volatile("cp.async.wait_group 0;\n" ::: "memory");
        __syncthreads();
        if (kt + 2 < NKT) {
            stage_A(Ablk, kt + 2, tid);
            asm volatile("cp.async.commit_group;\n" ::: "memory");
        }
        #pragma unroll
        for (int sub = 0; sub < 2; sub++) {
            // A half-chunk = 128 rows x 64 k = 16384 bytes; B half-chunk = 64 x 64 k = 8192 B
            const float4* A4 = reinterpret_cast<const float4*>(a_slot(kt) + sub * 16384);
            const float4* B4 = reinterpret_cast<const float4*>(
                dynsm + (size_t)kt * 16384 + sub * 8192);

            float4 af[2][2];      // double-buffered A frags per kc16
            float4 bq[2][4];      // B frags per kc32 pair (x,y = even kc16; z,w = odd)
            #pragma unroll
            for (int mb = 0; mb < 2; mb++) af[0][mb] = A4[(wm * 2 + mb) * 32 + lane];
            #pragma unroll
            for (int nb = 0; nb < 4; nb++) bq[0][nb] = B4[(wn * 4 + nb) * 32 + lane];

            #pragma unroll
            for (int kc = 0; kc < 4; kc++) {
                if (kc == 0) {
                    #pragma unroll
                    for (int nb = 0; nb < 4; nb++)
                        bq[1][nb] = B4[(8 + wn * 4 + nb) * 32 + lane];
                }
                if (kc < 3) {
                    #pragma unroll
                    for (int mb = 0; mb < 2; mb++)
                        af[(kc + 1) & 1][mb] = A4[((kc + 1) * 8 + wm * 2 + mb) * 32 + lane];
                }
                #pragma unroll
                for (int mb = 0; mb < 2; mb++)
                    #pragma unroll
                    for (int nb = 0; nb < 4; nb++) {
                        const float4& b4 = bq[kc >> 1][nb];
                        if (kc & 1) mma_f16(acc[mb][nb], af[kc & 1][mb], b4.z, b4.w);
                        else        mma_f16(acc[mb][nb], af[kc & 1][mb], b4.x, b4.y);
                    }
            }
        }
    }
    __syncthreads();   // all warps done reading A slots + B region before any reuse
}

// ---------------- persistent LSTM + projection ----------------
__global__ void __launch_bounds__(NTHR, 1)
lstm_persist(const float* __restrict__ b_out, float* __restrict__ probs_dst,
             float* __restrict__ hid_dst) {
    const int tid  = threadIdx.x;
    const int lane = tid & 31;
    const int w    = tid >> 5;
    const int wm   = w & 3;          // 4 m-warps (32 rows each)
    const int wn   = w >> 2;         // 2 n-warps (32 cols each)
    const int mt   = blockIdx.x;     // 0..1
    const int nt   = blockIdx.y;     // 0..63
    const int mBase = mt * BM;
    const int q    = (lane & 3) >> 1;          // h-group within 8-col span
    const int odd  = lane & 1;

    float* hout = (hid_dst != nullptr) ? hid_dst : g_out;

    float acc[2][4][4];
    float c_reg[8];                  // cell state: [mb*4+nb]
    #pragma unroll
    for (int i = 0; i < 8; i++) c_reg[i] = 0.f;

    // cached bias (steps >= 1): per nb the 4 gate biases of this thread's h-group
    float4 biasc[4];
    #pragma unroll
    for (int nb = 0; nb < 4; nb++) {
        int hl = wn * 8 + nb * 2 + q;
        biasc[nb] = *reinterpret_cast<const float4*>(&g_bp[nt * 64 + hl * 4]);
    }

    // load step-0 weights (w_hh) into persistent smem region
    stage_Bfull(g_Whp + (size_t)nt * B_NT_ELEMS, tid);
    asm volatile("cp.async.commit_group;\n" ::: "memory");

    #pragma unroll 1
    for (int t = 0; t < TSTEPS; t++) {
        const __half* A    = ((t & 1) ? g_act1 : g_act0) + (size_t)mt * A_MT_ELEMS;
        __half*       nact = (t & 1) ? g_act0 : g_act1;

        // prologue: stage A chunks 0..1 (B-full group is older)
        #pragma unroll
        for (int p = 0; p < 2; p++) {
            stage_A(A, p, tid);
            asm volatile("cp.async.commit_group;\n" ::: "memory");
        }
        gemm_loop(A, acc, tid, lane, wm, wn);

        // swap persistent B (overlaps epilogue + barrier)
        if (t == 0) {
            stage_Bfull(g_Wcp + (size_t)nt * B_NT_ELEMS, tid);
            asm volatile("cp.async.commit_group;\n" ::: "memory");
        } else if (t == TSTEPS - 1 && probs_dst != nullptr) {
            stage_Bfull(g_WoutP, tid);
            asm volatile("cp.async.commit_group;\n" ::: "memory");
        }

        // register epilogue: lane pairs exchange gate halves via shfl
        #pragma unroll
        for (int mb = 0; mb < 2; mb++)
            #pragma unroll
            for (int nb = 0; nb < 4; nb++) {
                float* a4 = acc[mb][nb];
                float s0 = odd ? a4[0] : a4[2];
                float s1 = odd ? a4[1] : a4[3];
                float r0 = __shfl_xor_sync(0xffffffffu, s0, 1);
                float r1 = __shfl_xor_sync(0xffffffffu, s1, 1);
                float gi, gf, gg, go;
                if (odd) { gi = r0;    gf = r1;    gg = a4[2]; go = a4[3]; }   // row r+8
                else     { gi = a4[0]; gf = a4[1]; gg = r0;    go = r1;   }   // row r
                int row = (wm * 2 + mb) * 16 + (lane >> 2) + (odd ? 8 : 0);
                int hl  = wn * 8 + nb * 2 + q;
                float4 bb = (t == 0)
                    ? *reinterpret_cast<const float4*>(&g_g0[nt * 64 + hl * 4])
                    : biasc[nb];
                gi += bb.x; gf += bb.y; gg += bb.z; go += bb.w;
                int ci = mb * 4 + nb;
                float cN = sigm(gf) * c_reg[ci] + sigm(gi) * tanh_acc(gg);
                float hN = sigm(go) * tanh_acc(cN);
                c_reg[ci] = cN;
                int b  = mBase + row;
                int hg = nt * 16 + hl;
                hout[((size_t)b * TSTEPS + t) * HID + hg] = hN;
                __half hv = __float2half_rn(hN);
                nact[a_idx(mt, row, hg)] = hv;
                int r2 = b * TSTEPS + t;
                g_A2[a_idx(r2 >> 7, r2 & 127, hg)] = hv;
            }

        // per-mt group barrier (64 CTAs): A(t+1) of this m-tile complete
        barrier_impl(&g_gbcount[mt * 32], &g_gbgen[mt * 32], 64u);
    }

    // projection: A2 [16384 x 1024] @ WoutP^T [64 x 1024] over 128 m-tiles
    if (probs_dst != nullptr) {
        barrier_impl(&g_bar_count, &g_bar_gen, (unsigned)NBLK);   // cross-group A2 ready
        int bid = mt + 2 * nt;               // 0..127
        const __half* A = g_A2 + (size_t)bid * A_MT_ELEMS;
        #pragma unroll
        for (int p = 0; p < 2; p++) {        // WoutP already loading into B region
            stage_A(A, p, tid);
            asm volatile("cp.async.commit_group;\n" ::: "memory");
        }
        gemm_loop(A, acc, tid, lane, wm, wn);
        int pBase = bid * BM;
        #pragma unroll
        for (int mb = 0; mb < 2; mb++)
            #pragma unroll
            for (int nb = 0; nb < 4; nb++) {
                int r0 = (wm * 2 + mb) * 16 + (lane >> 2);
                int c0 = wn * 32 + nb * 8 + (lane & 3) * 2;
                float2 b2 = *reinterpret_cast<const float2*>(&b_out[c0]);
                float2 v0 = make_float2(acc[mb][nb][0] + b2.x, acc[mb][nb][1] + b2.y);
                float2 v1 = make_float2(acc[mb][nb][2] + b2.x, acc[mb][nb][3] + b2.y);
                *reinterpret_cast<float2*>(&probs_dst[(size_t)(pBase + r0) * OUTW + c0]) = v0;
                *reinterpret_cast<float2*>(&probs_dst[(size_t)(pBase + r0 + 8) * OUTW + c0]) = v1;
            }
    }
}

// ---------------- host ----------------
extern "C" void kernel_launch(void* const* d_in, const int* in_sizes, int n_in,
                              void* d_out, int out_size) {
    const float* qf    = (const float*)d_in[1];
    const float* st    = (const float*)d_in[4];
    const float* w_in  = (const float*)d_in[5];
    const float* b_in  = (const float*)d_in[6];
    const float* w_ih  = (const float*)d_in[7];
    const float* w_hh  = (const float*)d_in[8];
    const float* b_ih  = (const float*)d_in[9];
    const float* b_hh  = (const float*)d_in[10];
    const float* w_out = (const float*)d_in[11];
    const float* b_out = (const float*)d_in[12];
    float* out = (float*)d_out;

    cudaFuncSetAttribute(lstm_persist, cudaFuncAttributeMaxDynamicSharedMemorySize, SMEM_BYTES);

    prep_weights<<<(N4 * HID) / 256, 256>>>(w_ih, w_hh);
    prep_wout<<<(OUTW * HID) / 256, 256>>>(w_out);
    prep_bias<<<128, 256>>>(st, w_ih, b_ih, b_hh);
    h0_part<<<dim3(BSZ, H0S), 256>>>(qf, w_in);
    h0_comb<<<BSZ, 256>>>(b_in);

    // output routing: reference returns (probs, output)
    const long long PROBS_N = (long long)BSZ * TSTEPS * OUTW;
    const long long OUT_N   = (long long)BSZ * TSTEPS * HID;
    float* probs_dst = nullptr;
    float* hid_dst   = nullptr;
    if ((long long)out_size >= PROBS_N + OUT_N) {
        probs_dst = out;
        hid_dst   = out + PROBS_N;
    } else if ((long long)out_size == OUT_N) {
        hid_dst = out;
    } else {
        probs_dst = out;
    }

    lstm_persist<<<dim3(2, 64), NTHR, SMEM_BYTES>>>(b_out, probs_dst, hid_dst);
}